// round 5
// baseline (speedup 1.0000x reference)
#include <cuda_runtime.h>

#define NN 50000
#define NE 200000
#define H  128
#define HV4 32   // H/4

// Scratch (device globals: allocation-free per harness rules)
__device__ float g_node_h[NN * H];        // 25.6 MB
__device__ float g_agg[NN * H];           // 25.6 MB  per-layer atomic accumulator
__device__ float g_agg_base[NN * H];      // 25.6 MB  Σ edge_h per dst (factorized)
__device__ float g_escratch[NN * 65];     // precompute: eaggF [NN,64] + deg [NN]; later: sdot2 [NN]x2
__device__ float g_edot[NE];              // folded edge-constant gate logit
__device__ float g_wcombo[65];            // W_edge @ w_top_e (64) + folded bias

// packed fp32x2 FMA: d = a*b + d (elementwise on 2 floats in a b64 reg)
__device__ __forceinline__ void ffma2(unsigned long long& d,
                                      unsigned long long a,
                                      unsigned long long b) {
    asm("fma.rn.f32x2 %0, %1, %2, %0;" : "+l"(d) : "l"(a), "l"(b));
}
__device__ __forceinline__ float ull_lo(unsigned long long u) {
    return __uint_as_float((unsigned)(u & 0xffffffffu));
}
__device__ __forceinline__ float ull_hi(unsigned long long u) {
    return __uint_as_float((unsigned)(u >> 32));
}
__device__ __forceinline__ void red_v4(float* p, float a, float b, float c, float d) {
    asm volatile("red.global.add.v4.f32 [%0], {%1,%2,%3,%4};"
                 :: "l"(p), "f"(a), "f"(b), "f"(c), "f"(d) : "memory");
}
__device__ __forceinline__ void red_v2(float* p, float a, float b) {
    asm volatile("red.global.add.v2.f32 [%0], {%1,%2};"
                 :: "l"(p), "f"(a), "f"(b) : "memory");
}

__global__ void zero_kernel(float4* __restrict__ p, int n4) {
    int i = blockIdx.x * blockDim.x + threadIdx.x;
    if (i < n4) p[i] = make_float4(0.f, 0.f, 0.f, 0.f);
}

// ---------------------------------------------------------------------------
// wcombo[k] = sum_h W_edge[k,h] * W_top[2H+h];  wcombo[64] = folded bias
// ---------------------------------------------------------------------------
__global__ void combo_kernel(const float* __restrict__ W_edge,
                             const float* __restrict__ W_top,
                             const float* __restrict__ b_edge,
                             const float* __restrict__ b_top,
                             float* __restrict__ wcombo)
{
    const int k = threadIdx.x;   // 64 threads
    float s = 0.f;
    for (int h = 0; h < H; h++) s += W_edge[k * H + h] * W_top[2 * H + h];
    wcombo[k] = s;
    if (k == 0) {
        float b = b_top[0];
        for (int h = 0; h < H; h++) b += b_edge[h] * W_top[2 * H + h];
        wcombo[64] = b;
    }
}

// ---------------------------------------------------------------------------
// Per-edge precompute (once): edot[e] = ef[e].wcombo + bias_const; scatter raw
// edge_features into eaggF[dst] (red.v2), deg[dst] += 1.
// ---------------------------------------------------------------------------
__global__ void edge_pre_kernel(const float* __restrict__ ef,
                                const int* __restrict__ dst,
                                const float* __restrict__ wcombo,
                                float* __restrict__ eaggF,
                                float* __restrict__ deg,
                                float* __restrict__ edot)
{
    __shared__ float wsh[65];
    const int tid  = threadIdx.x;
    const int lane = tid & 31;
    const int wid  = tid >> 5;
    if (tid < 65) wsh[tid] = wcombo[tid];
    __syncthreads();

    const int e = blockIdx.x * 8 + wid;
    const int d = dst[e];
    float2 v = ((const float2*)ef)[(size_t)e * 32 + lane];
    float p = v.x * wsh[lane * 2] + v.y * wsh[lane * 2 + 1];
    #pragma unroll
    for (int off = 16; off; off >>= 1)
        p += __shfl_xor_sync(0xffffffffu, p, off);
    if (lane == 0) {
        edot[e] = p + wsh[64];
        atomicAdd(deg + d, 1.f);
    }
    red_v2(eaggF + (size_t)d * 64 + lane * 2, v.x, v.y);
}

// ---------------------------------------------------------------------------
// Embed GEMM (FFMA2): out[rows,H] = X[rows,K] @ W[K,H] + scale*b
// 256 threads, 64-row chunks, 8 rows/warp, 4 cols/lane. X staged duplicated
// ({x,x} b64) so the inner loop is LDS + FFMA2 only.
// DEGBIAS: bias scaled by deg[row]. SDOT: epilogue writes {o.ws, o.wd}.
// ---------------------------------------------------------------------------
template<int K, bool DEGBIAS, bool SDOT>
__global__ void embed_kernel(const float* __restrict__ X,
                             const float* __restrict__ W,
                             const float* __restrict__ b,
                             const float* __restrict__ deg,
                             const float* __restrict__ W_top,
                             float* __restrict__ out,
                             float2* __restrict__ sdot2, int rows)
{
    extern __shared__ float sm[];
    float* Wsh = sm;                                       // K*H floats
    unsigned long long* xdup = (unsigned long long*)(sm + K * H);  // [64][K]

    const int tid  = threadIdx.x;
    const int lane = tid & 31;
    const int wid  = tid >> 5;

    for (int i = tid; i < K * H / 4; i += 256)
        ((float4*)Wsh)[i] = ((const float4*)W)[i];
    const float4 bias = ((const float4*)b)[lane];
    float4 wsA, wdA;
    if (SDOT) {
        wsA = ((const float4*)W_top)[lane];
        wdA = ((const float4*)W_top)[32 + lane];
    }

    for (int r0 = blockIdx.x * 64; r0 < rows; r0 += gridDim.x * 64) {
        __syncthreads();
        const int nrows = min(64, rows - r0);
        for (int i = tid; i < nrows * (K / 4); i += 256) {
            const int r = i / (K / 4), c = i % (K / 4);
            float4 v = ((const float4*)(X + (size_t)(r0 + r) * K))[c];
            float2* dr = (float2*)(xdup + (size_t)r * K + c * 4);
            dr[0] = make_float2(v.x, v.x);
            dr[1] = make_float2(v.y, v.y);
            dr[2] = make_float2(v.z, v.z);
            dr[3] = make_float2(v.w, v.w);
        }
        __syncthreads();

        const int rbase = wid * 8;
        unsigned long long acc[8][2];
        #pragma unroll
        for (int r = 0; r < 8; r++) { acc[r][0] = 0ull; acc[r][1] = 0ull; }

        #pragma unroll 2
        for (int k = 0; k < K; k++) {
            ulonglong2 wv = ((const ulonglong2*)(Wsh + (size_t)k * H))[lane];
            #pragma unroll
            for (int r = 0; r < 8; r++) {
                unsigned long long xx = xdup[(size_t)(rbase + r) * K + k];
                ffma2(acc[r][0], wv.x, xx);
                ffma2(acc[r][1], wv.y, xx);
            }
        }

        #pragma unroll
        for (int r = 0; r < 8; r++) {
            const int row = rbase + r;
            if (row < nrows) {
                const float scb = DEGBIAS ? deg[r0 + row] : 1.f;
                float4 o;
                o.x = ull_lo(acc[r][0]) + scb * bias.x;
                o.y = ull_hi(acc[r][0]) + scb * bias.y;
                o.z = ull_lo(acc[r][1]) + scb * bias.z;
                o.w = ull_hi(acc[r][1]) + scb * bias.w;
                ((float4*)out)[(size_t)(r0 + row) * HV4 + lane] = o;
                if (SDOT) {
                    float s1 = o.x * wsA.x + o.y * wsA.y + o.z * wsA.z + o.w * wsA.w;
                    float s2 = o.x * wdA.x + o.y * wdA.y + o.z * wdA.z + o.w * wdA.w;
                    #pragma unroll
                    for (int off = 16; off; off >>= 1) {
                        s1 += __shfl_xor_sync(0xffffffffu, s1, off);
                        s2 += __shfl_xor_sync(0xffffffffu, s2, off);
                    }
                    if (lane == 0) sdot2[r0 + row] = make_float2(s1, s2);
                }
            }
        }
    }
}

// ---------------------------------------------------------------------------
// Slim per-layer edge kernel: w = sigmoid(sdot2[s].x + sdot2[d].y + edot[e]);
// RED src_f * w into agg (zeroed). One warp per edge, red.v4 per lane.
// ---------------------------------------------------------------------------
template<bool WRITE_EW>
__global__ void edge_slim_kernel(const float* __restrict__ node_h,
                                 const int* __restrict__ src,
                                 const int* __restrict__ dst,
                                 const float2* __restrict__ sdot2,
                                 const float* __restrict__ edot,
                                 float* __restrict__ agg,
                                 float* __restrict__ ew)
{
    const int tid  = threadIdx.x;
    const int lane = tid & 31;
    const int wid  = tid >> 5;
    const int e = blockIdx.x * 8 + wid;

    const int s = src[e];
    const int d = dst[e];
    const float2 ss = sdot2[s];
    const float2 dd = sdot2[d];
    const float p = ss.x + dd.y + edot[e];
    const float w = 1.f / (1.f + __expf(-p));

    float4 sf = ((const float4*)node_h)[(size_t)s * HV4 + lane];
    red_v4(agg + (size_t)d * H + lane * 4, sf.x * w, sf.y * w, sf.z * w, sf.w * w);

    if (WRITE_EW && lane == 0) ew[e] = w;
}

// ---------------------------------------------------------------------------
// GNN dense (FFMA2) + residual + LayerNorm + ReLU + sdot epilogue.
// updated = [node_h | agg+agg_base] @ W[256,128] + b.
// 256 threads, 64-row chunks, 8 rows/warp. K processed in two halves of 128
// (xdup holds one half, duplicated). Clears agg in-place for next layer.
// ---------------------------------------------------------------------------
template<bool LAST>
__global__ void gnn_kernel(const float* __restrict__ node_h,
                           float* __restrict__ agg,
                           const float* __restrict__ agg_base,
                           const float* __restrict__ W,     // [256,128]
                           const float* __restrict__ b,
                           const float* __restrict__ lns,
                           const float* __restrict__ lnb,
                           const float* __restrict__ W_top,
                           float* __restrict__ out,
                           float2* __restrict__ sdot2, int rows)
{
    extern __shared__ float sm[];
    float* Wsh = sm;                                           // 256*128 = 128 KB
    unsigned long long* xdup = (unsigned long long*)(sm + 256 * H);  // [64][128] = 64 KB

    const int tid  = threadIdx.x;
    const int lane = tid & 31;
    const int wid  = tid >> 5;

    for (int i = tid; i < 256 * H / 4; i += 256)
        ((float4*)Wsh)[i] = ((const float4*)W)[i];
    const float4 bias = ((const float4*)b)[lane];
    const float4 sc   = ((const float4*)lns)[lane];
    const float4 bi   = ((const float4*)lnb)[lane];
    const float4 wsA  = ((const float4*)W_top)[lane];
    const float4 wdA  = ((const float4*)W_top)[32 + lane];

    for (int r0 = blockIdx.x * 64; r0 < rows; r0 += gridDim.x * 64) {
        __syncthreads();
        const int nrows = min(64, rows - r0);
        const int rbase = wid * 8;

        // half 0: node_h columns
        for (int i = tid; i < nrows * HV4; i += 256) {
            const int r = i >> 5, c = i & 31;
            float4 v = ((const float4*)node_h)[(size_t)(r0 + r) * HV4 + c];
            float2* dr = (float2*)(xdup + (size_t)r * H + c * 4);
            dr[0] = make_float2(v.x, v.x);
            dr[1] = make_float2(v.y, v.y);
            dr[2] = make_float2(v.z, v.z);
            dr[3] = make_float2(v.w, v.w);
        }
        __syncthreads();

        unsigned long long acc[8][2];
        #pragma unroll
        for (int r = 0; r < 8; r++) { acc[r][0] = 0ull; acc[r][1] = 0ull; }

        #pragma unroll 2
        for (int k = 0; k < 128; k++) {
            ulonglong2 wv = ((const ulonglong2*)(Wsh + (size_t)k * H))[lane];
            #pragma unroll
            for (int r = 0; r < 8; r++) {
                unsigned long long xx = xdup[(size_t)(rbase + r) * H + k];
                ffma2(acc[r][0], wv.x, xx);
                ffma2(acc[r][1], wv.y, xx);
            }
        }

        __syncthreads();
        // half 1: agg + agg_base columns (and clear agg for the next layer)
        for (int i = tid; i < nrows * HV4; i += 256) {
            const int r = i >> 5, c = i & 31;
            float4 a = ((const float4*)agg)[(size_t)(r0 + r) * HV4 + c];
            float4 ab = ((const float4*)agg_base)[(size_t)(r0 + r) * HV4 + c];
            a.x += ab.x; a.y += ab.y; a.z += ab.z; a.w += ab.w;
            float2* dr = (float2*)(xdup + (size_t)r * H + c * 4);
            dr[0] = make_float2(a.x, a.x);
            dr[1] = make_float2(a.y, a.y);
            dr[2] = make_float2(a.z, a.z);
            dr[3] = make_float2(a.w, a.w);
            if (!LAST)
                ((float4*)agg)[(size_t)(r0 + r) * HV4 + c] = make_float4(0.f, 0.f, 0.f, 0.f);
        }
        __syncthreads();

        #pragma unroll 2
        for (int k = 0; k < 128; k++) {
            ulonglong2 wv = ((const ulonglong2*)(Wsh + (size_t)(128 + k) * H))[lane];
            #pragma unroll
            for (int r = 0; r < 8; r++) {
                unsigned long long xx = xdup[(size_t)(rbase + r) * H + k];
                ffma2(acc[r][0], wv.x, xx);
                ffma2(acc[r][1], wv.y, xx);
            }
        }

        #pragma unroll
        for (int r = 0; r < 8; r++) {
            const int row = rbase + r;
            if (row < nrows) {
                float4 res = ((const float4*)node_h)[(size_t)(r0 + row) * HV4 + lane];
                float4 v;
                v.x = res.x + ull_lo(acc[r][0]) + bias.x;
                v.y = res.y + ull_hi(acc[r][0]) + bias.y;
                v.z = res.z + ull_lo(acc[r][1]) + bias.z;
                v.w = res.w + ull_hi(acc[r][1]) + bias.w;
                float s  = v.x + v.y + v.z + v.w;
                float ssum = v.x * v.x + v.y * v.y + v.z * v.z + v.w * v.w;
                #pragma unroll
                for (int off = 16; off; off >>= 1) {
                    s    += __shfl_xor_sync(0xffffffffu, s, off);
                    ssum += __shfl_xor_sync(0xffffffffu, ssum, off);
                }
                const float mean = s * (1.f / 128.f);
                const float var  = ssum * (1.f / 128.f) - mean * mean;
                const float rstd = rsqrtf(var + 1e-6f);
                float4 o;
                o.x = fmaxf((v.x - mean) * rstd * sc.x + bi.x, 0.f);
                o.y = fmaxf((v.y - mean) * rstd * sc.y + bi.y, 0.f);
                o.z = fmaxf((v.z - mean) * rstd * sc.z + bi.z, 0.f);
                o.w = fmaxf((v.w - mean) * rstd * sc.w + bi.w, 0.f);
                ((float4*)out)[(size_t)(r0 + row) * HV4 + lane] = o;
                if (!LAST) {
                    float s1 = o.x * wsA.x + o.y * wsA.y + o.z * wsA.z + o.w * wsA.w;
                    float s2 = o.x * wdA.x + o.y * wdA.y + o.z * wdA.z + o.w * wdA.w;
                    #pragma unroll
                    for (int off = 16; off; off >>= 1) {
                        s1 += __shfl_xor_sync(0xffffffffu, s1, off);
                        s2 += __shfl_xor_sync(0xffffffffu, s2, off);
                    }
                    if (lane == 0) sdot2[r0 + row] = make_float2(s1, s2);
                }
            }
        }
    }
}

extern "C" void kernel_launch(void* const* d_in, const int* in_sizes, int n_in,
                              void* d_out, int out_size)
{
    const float* node_features = (const float*)d_in[0];
    const float* edge_features = (const float*)d_in[1];
    const int*   edge_indices  = (const int*)d_in[2];
    const float* W_node   = (const float*)d_in[3];
    const float* b_node   = (const float*)d_in[4];
    const float* W_edge   = (const float*)d_in[5];
    const float* b_edge   = (const float*)d_in[6];
    const float* W_gnn    = (const float*)d_in[7];
    const float* b_gnn    = (const float*)d_in[8];
    const float* W_top    = (const float*)d_in[9];
    const float* b_top    = (const float*)d_in[10];
    const float* ln_scale = (const float*)d_in[11];
    const float* ln_bias  = (const float*)d_in[12];

    float *node_h, *agg, *agg_base, *escratch, *edot, *wcombo;
    cudaGetSymbolAddress((void**)&node_h,   g_node_h);
    cudaGetSymbolAddress((void**)&agg,      g_agg);
    cudaGetSymbolAddress((void**)&agg_base, g_agg_base);
    cudaGetSymbolAddress((void**)&escratch, g_escratch);
    cudaGetSymbolAddress((void**)&edot,     g_edot);
    cudaGetSymbolAddress((void**)&wcombo,   g_wcombo);
    float* eaggF   = escratch;             // [NN, 64] (precompute phase)
    float* deg     = escratch + NN * 64;   // [NN]
    float2* sdot2  = (float2*)escratch;    // [NN] (layer phase; reuses eaggF region)

    float* out_node = (float*)d_out;                       // [NN, H]
    float* out_ew   = (float*)d_out + (size_t)NN * H;      // [NE]

    const int* srcp = edge_indices;
    const int* dstp = edge_indices + NE;

    const int smem_e128 = (128 * H) * 4 + 64 * 128 * 8;    // 64 + 64 = 128 KB
    const int smem_e64  = (64 * H) * 4 + 64 * 64 * 8;      // 32 + 32 = 64 KB
    const int smem_gnn  = (256 * H) * 4 + 64 * 128 * 8;    // 128 + 64 = 192 KB
    cudaFuncSetAttribute((const void*)embed_kernel<128, false, true>,
                         cudaFuncAttributeMaxDynamicSharedMemorySize, smem_e128);
    cudaFuncSetAttribute((const void*)embed_kernel<64, true, false>,
                         cudaFuncAttributeMaxDynamicSharedMemorySize, smem_e64);
    cudaFuncSetAttribute((const void*)gnn_kernel<false>,
                         cudaFuncAttributeMaxDynamicSharedMemorySize, smem_gnn);
    cudaFuncSetAttribute((const void*)gnn_kernel<true>,
                         cudaFuncAttributeMaxDynamicSharedMemorySize, smem_gnn);

    // --- one-time precompute ---
    combo_kernel<<<1, 64>>>(W_edge, W_top, b_edge, b_top, wcombo);
    zero_kernel<<<(NN * 65 / 4 + 255) / 256, 256>>>((float4*)escratch, NN * 65 / 4);
    zero_kernel<<<NN * H / 4 / 256, 256>>>((float4*)agg, NN * H / 4);
    edge_pre_kernel<<<NE / 8, 256>>>(edge_features, dstp, wcombo, eaggF, deg, edot);
    embed_kernel<64, true, false><<<444, 256, smem_e64>>>(
        eaggF, W_edge, b_edge, deg, nullptr, agg_base, nullptr, NN);
    embed_kernel<128, false, true><<<296, 256, smem_e128>>>(
        node_features, W_node, b_node, nullptr, W_top, node_h, sdot2, NN);

    // --- layers ---
    for (int i = 0; i < 3; i++) {
        if (i == 2)
            edge_slim_kernel<true><<<NE / 8, 256>>>(node_h, srcp, dstp, sdot2, edot, agg, out_ew);
        else
            edge_slim_kernel<false><<<NE / 8, 256>>>(node_h, srcp, dstp, sdot2, edot, agg, out_ew);
        const float* Wl  = W_gnn + (size_t)i * 256 * H;
        const float* bl  = b_gnn + i * H;
        const float* lsl = ln_scale + i * H;
        const float* lbl = ln_bias + i * H;
        if (i == 2)
            gnn_kernel<true><<<148, 256, smem_gnn>>>(node_h, agg, agg_base, Wl, bl, lsl, lbl,
                                                     W_top, out_node, sdot2, NN);
        else
            gnn_kernel<false><<<148, 256, smem_gnn>>>(node_h, agg, agg_base, Wl, bl, lsl, lbl,
                                                      W_top, node_h, sdot2, NN);
    }
}

// round 6
// speedup vs baseline: 1.2436x; 1.2436x over previous
#include <cuda_runtime.h>

#define NN 50000
#define NE 200000
#define H  128
#define HV4 32   // H/4

// Scratch (device globals: allocation-free per harness rules)
__device__ float g_node_h[NN * H];        // 25.6 MB
__device__ float g_agg[NN * H];           // 25.6 MB  per-layer atomic accumulator
__device__ float g_agg_base[NN * H];      // 25.6 MB  Σ edge_h per dst (factorized)
__device__ float g_escratch[NN * 65];     // precompute: eaggF [NN,64] + deg [NN]; layers: sdot2 [NN]
__device__ float g_edot[NE];              // folded edge-constant gate logit
__device__ float g_wcombo[65];            // W_edge @ w_top_e (64) + folded bias

__device__ __forceinline__ void fma4(float4& acc, const float4& wv, float s) {
    acc.x += wv.x * s;
    acc.y += wv.y * s;
    acc.z += wv.z * s;
    acc.w += wv.w * s;
}
__device__ __forceinline__ void red_v4(float* p, float a, float b, float c, float d) {
    asm volatile("red.global.add.v4.f32 [%0], {%1,%2,%3,%4};"
                 :: "l"(p), "f"(a), "f"(b), "f"(c), "f"(d) : "memory");
}
__device__ __forceinline__ void red_v2(float* p, float a, float b) {
    asm volatile("red.global.add.v2.f32 [%0], {%1,%2};"
                 :: "l"(p), "f"(a), "f"(b) : "memory");
}

__global__ void zero_kernel(float4* __restrict__ p, int n4) {
    int i = blockIdx.x * blockDim.x + threadIdx.x;
    if (i < n4) p[i] = make_float4(0.f, 0.f, 0.f, 0.f);
}

// ---------------------------------------------------------------------------
// wcombo[k] = sum_h W_edge[k,h] * W_top[2H+h];  wcombo[64] = folded bias
// ---------------------------------------------------------------------------
__global__ void combo_kernel(const float* __restrict__ W_edge,
                             const float* __restrict__ W_top,
                             const float* __restrict__ b_edge,
                             const float* __restrict__ b_top,
                             float* __restrict__ wcombo)
{
    const int k = threadIdx.x;   // 64 threads
    float s = 0.f;
    for (int h = 0; h < H; h++) s += W_edge[k * H + h] * W_top[2 * H + h];
    wcombo[k] = s;
    if (k == 0) {
        float b = b_top[0];
        for (int h = 0; h < H; h++) b += b_edge[h] * W_top[2 * H + h];
        wcombo[64] = b;
    }
}

// ---------------------------------------------------------------------------
// Per-edge precompute (once): edot[e] = ef[e].wcombo + bias_const; scatter raw
// edge_features into eaggF[dst] (red.v2), deg[dst] += 1.
// ---------------------------------------------------------------------------
__global__ void edge_pre_kernel(const float* __restrict__ ef,
                                const int* __restrict__ dst,
                                const float* __restrict__ wcombo,
                                float* __restrict__ eaggF,
                                float* __restrict__ deg,
                                float* __restrict__ edot)
{
    __shared__ float wsh[65];
    const int tid  = threadIdx.x;
    const int lane = tid & 31;
    const int wid  = tid >> 5;
    if (tid < 65) wsh[tid] = wcombo[tid];
    __syncthreads();

    const int e = blockIdx.x * 8 + wid;
    const int d = dst[e];
    float2 v = ((const float2*)ef)[(size_t)e * 32 + lane];
    float p = v.x * wsh[lane * 2] + v.y * wsh[lane * 2 + 1];
    #pragma unroll
    for (int off = 16; off; off >>= 1)
        p += __shfl_xor_sync(0xffffffffu, p, off);
    if (lane == 0) {
        edot[e] = p + wsh[64];
        atomicAdd(deg + d, 1.f);
    }
    red_v2(eaggF + (size_t)d * 64 + lane * 2, v.x, v.y);
}

// ---------------------------------------------------------------------------
// Embed GEMM (R3-proven formulation): out[rows,H] = X[rows,K] @ W[K,H] + scale*b
// 256 threads, 32-row chunks, 4 rows/warp, 4 cols/lane. W + X staged in smem.
// DEGBIAS: bias scaled by deg[row]. SDOT: epilogue writes {o.ws, o.wd}.
// ---------------------------------------------------------------------------
template<int K, bool DEGBIAS, bool SDOT>
__global__ void embed_kernel(const float* __restrict__ X,
                             const float* __restrict__ W,
                             const float* __restrict__ b,
                             const float* __restrict__ deg,
                             const float* __restrict__ W_top,
                             float* __restrict__ out,
                             float2* __restrict__ sdot2, int rows)
{
    extern __shared__ float sm[];
    float* Wsh  = sm;            // K*H floats
    float* xbuf = sm + K * H;    // 32*K floats

    const int tid  = threadIdx.x;
    const int lane = tid & 31;
    const int wid  = tid >> 5;

    for (int i = tid; i < K * H / 4; i += 256)
        ((float4*)Wsh)[i] = ((const float4*)W)[i];
    const float4 bias = ((const float4*)b)[lane];
    float4 wsA, wdA;
    if (SDOT) {
        wsA = ((const float4*)W_top)[lane];
        wdA = ((const float4*)W_top)[32 + lane];
    }

    for (int r0 = blockIdx.x * 32; r0 < rows; r0 += gridDim.x * 32) {
        __syncthreads();
        const int nrows = min(32, rows - r0);
        for (int i = tid; i < nrows * (K / 4); i += 256)
            ((float4*)xbuf)[i] = ((const float4*)(X + (size_t)r0 * K))[i];
        __syncthreads();

        const int rbase = wid * 4;
        if (rbase < nrows) {   // nrows multiple of 4 for tails here (50000 % 32 = 16)
            float4 acc0 = make_float4(0.f, 0.f, 0.f, 0.f);
            float4 acc1 = acc0, acc2 = acc0, acc3 = acc0;
            const float* xr0 = xbuf + (rbase + 0) * K;
            const float* xr1 = xbuf + (rbase + 1) * K;
            const float* xr2 = xbuf + (rbase + 2) * K;
            const float* xr3 = xbuf + (rbase + 3) * K;
            #pragma unroll 4
            for (int k = 0; k < K; k++) {
                float4 wv = ((float4*)Wsh)[k * HV4 + lane];
                fma4(acc0, wv, xr0[k]);
                fma4(acc1, wv, xr1[k]);
                fma4(acc2, wv, xr2[k]);
                fma4(acc3, wv, xr3[k]);
            }
            float4 accs[4] = {acc0, acc1, acc2, acc3};
            #pragma unroll
            for (int rr = 0; rr < 4; rr++) {
                const float scb = DEGBIAS ? deg[r0 + rbase + rr] : 1.f;
                float4 o;
                o.x = accs[rr].x + scb * bias.x;
                o.y = accs[rr].y + scb * bias.y;
                o.z = accs[rr].z + scb * bias.z;
                o.w = accs[rr].w + scb * bias.w;
                ((float4*)out)[(size_t)(r0 + rbase + rr) * HV4 + lane] = o;
                if (SDOT) {
                    float s1 = o.x * wsA.x + o.y * wsA.y + o.z * wsA.z + o.w * wsA.w;
                    float s2 = o.x * wdA.x + o.y * wdA.y + o.z * wdA.z + o.w * wdA.w;
                    #pragma unroll
                    for (int off = 16; off; off >>= 1) {
                        s1 += __shfl_xor_sync(0xffffffffu, s1, off);
                        s2 += __shfl_xor_sync(0xffffffffu, s2, off);
                    }
                    if (lane == 0) sdot2[r0 + rbase + rr] = make_float2(s1, s2);
                }
            }
        }
    }
}

// ---------------------------------------------------------------------------
// Slim per-layer edge kernel: w = sigmoid(sdot2[s].x + sdot2[d].y + edot[e]);
// RED src_f * w into agg (pre-zeroed). One warp per edge, red.v4 per lane.
// ---------------------------------------------------------------------------
template<bool WRITE_EW>
__global__ void edge_slim_kernel(const float* __restrict__ node_h,
                                 const int* __restrict__ src,
                                 const int* __restrict__ dst,
                                 const float2* __restrict__ sdot2,
                                 const float* __restrict__ edot,
                                 float* __restrict__ agg,
                                 float* __restrict__ ew)
{
    const int tid  = threadIdx.x;
    const int lane = tid & 31;
    const int wid  = tid >> 5;
    const int e = blockIdx.x * 8 + wid;

    const int s = src[e];
    const int d = dst[e];
    const float2 ss = sdot2[s];
    const float2 dd = sdot2[d];
    const float p = ss.x + dd.y + edot[e];
    const float w = 1.f / (1.f + __expf(-p));

    float4 sf = ((const float4*)node_h)[(size_t)s * HV4 + lane];
    red_v4(agg + (size_t)d * H + lane * 4, sf.x * w, sf.y * w, sf.z * w, sf.w * w);

    if (WRITE_EW && lane == 0) ew[e] = w;
}

// ---------------------------------------------------------------------------
// GNN dense + residual + LayerNorm + ReLU + sdot epilogue (R3-proven core).
// updated = [node_h | agg+agg_base] @ W[256,128] + b.
// 512 threads, 64-row chunks, 4 rows/warp. Clears agg for the next layer.
// ---------------------------------------------------------------------------
template<bool LAST>
__global__ void gnn_kernel(const float* __restrict__ node_h,
                           float* __restrict__ agg,
                           const float* __restrict__ agg_base,
                           const float* __restrict__ W,     // [256,128]
                           const float* __restrict__ b,
                           const float* __restrict__ lns,
                           const float* __restrict__ lnb,
                           const float* __restrict__ W_top,
                           float* __restrict__ out,
                           float2* __restrict__ sdot2, int rows)
{
    extern __shared__ float sm[];
    float* Wsh  = sm;              // 256*128 floats = 128 KB
    float* xbuf = sm + 256 * H;    // 64*256 floats = 64 KB

    const int tid  = threadIdx.x;
    const int lane = tid & 31;
    const int wid  = tid >> 5;

    for (int i = tid; i < 256 * H / 4; i += 512)
        ((float4*)Wsh)[i] = ((const float4*)W)[i];
    const float4 bias = ((const float4*)b)[lane];
    const float4 sc   = ((const float4*)lns)[lane];
    const float4 bi   = ((const float4*)lnb)[lane];
    const float4 wsA  = ((const float4*)W_top)[lane];
    const float4 wdA  = ((const float4*)W_top)[32 + lane];

    for (int r0 = blockIdx.x * 64; r0 < rows; r0 += gridDim.x * 64) {
        __syncthreads();
        const int nrows = min(64, rows - r0);
        for (int i = tid; i < nrows * HV4; i += 512) {
            const int r = i >> 5, c = i & 31;
            ((float4*)(xbuf + r * 256))[c] = ((const float4*)node_h)[(size_t)(r0 + r) * HV4 + c];
            float4 a  = ((const float4*)agg)[(size_t)(r0 + r) * HV4 + c];
            float4 ab = ((const float4*)agg_base)[(size_t)(r0 + r) * HV4 + c];
            a.x += ab.x; a.y += ab.y; a.z += ab.z; a.w += ab.w;
            ((float4*)(xbuf + r * 256 + H))[c] = a;
            if (!LAST)
                ((float4*)agg)[(size_t)(r0 + r) * HV4 + c] = make_float4(0.f, 0.f, 0.f, 0.f);
        }
        __syncthreads();

        const int rbase = wid * 4;
        if (rbase < nrows) {
            float4 acc0 = make_float4(0.f, 0.f, 0.f, 0.f);
            float4 acc1 = acc0, acc2 = acc0, acc3 = acc0;
            const float* xr0 = xbuf + (rbase + 0) * 256;
            const float* xr1 = xbuf + (rbase + 1) * 256;
            const float* xr2 = xbuf + (rbase + 2) * 256;
            const float* xr3 = xbuf + (rbase + 3) * 256;
            #pragma unroll 4
            for (int k = 0; k < 256; k++) {
                float4 wv = ((float4*)Wsh)[k * HV4 + lane];
                fma4(acc0, wv, xr0[k]);
                fma4(acc1, wv, xr1[k]);
                fma4(acc2, wv, xr2[k]);
                fma4(acc3, wv, xr3[k]);
            }
            float4 accs[4] = {acc0, acc1, acc2, acc3};
            #pragma unroll
            for (int rr = 0; rr < 4; rr++) {
                float4 res = ((float4*)(xbuf + (rbase + rr) * 256))[lane];
                float4 v;
                v.x = res.x + accs[rr].x + bias.x;
                v.y = res.y + accs[rr].y + bias.y;
                v.z = res.z + accs[rr].z + bias.z;
                v.w = res.w + accs[rr].w + bias.w;
                float s    = v.x + v.y + v.z + v.w;
                float ssum = v.x * v.x + v.y * v.y + v.z * v.z + v.w * v.w;
                #pragma unroll
                for (int off = 16; off; off >>= 1) {
                    s    += __shfl_xor_sync(0xffffffffu, s, off);
                    ssum += __shfl_xor_sync(0xffffffffu, ssum, off);
                }
                const float mean = s * (1.f / 128.f);
                const float var  = ssum * (1.f / 128.f) - mean * mean;
                const float rstd = rsqrtf(var + 1e-6f);
                float4 o;
                o.x = fmaxf((v.x - mean) * rstd * sc.x + bi.x, 0.f);
                o.y = fmaxf((v.y - mean) * rstd * sc.y + bi.y, 0.f);
                o.z = fmaxf((v.z - mean) * rstd * sc.z + bi.z, 0.f);
                o.w = fmaxf((v.w - mean) * rstd * sc.w + bi.w, 0.f);
                ((float4*)out)[(size_t)(r0 + rbase + rr) * HV4 + lane] = o;
                if (!LAST) {
                    float s1 = o.x * wsA.x + o.y * wsA.y + o.z * wsA.z + o.w * wsA.w;
                    float s2 = o.x * wdA.x + o.y * wdA.y + o.z * wdA.z + o.w * wdA.w;
                    #pragma unroll
                    for (int off = 16; off; off >>= 1) {
                        s1 += __shfl_xor_sync(0xffffffffu, s1, off);
                        s2 += __shfl_xor_sync(0xffffffffu, s2, off);
                    }
                    if (lane == 0) sdot2[r0 + rbase + rr] = make_float2(s1, s2);
                }
            }
        }
    }
}

extern "C" void kernel_launch(void* const* d_in, const int* in_sizes, int n_in,
                              void* d_out, int out_size)
{
    const float* node_features = (const float*)d_in[0];
    const float* edge_features = (const float*)d_in[1];
    const int*   edge_indices  = (const int*)d_in[2];
    const float* W_node   = (const float*)d_in[3];
    const float* b_node   = (const float*)d_in[4];
    const float* W_edge   = (const float*)d_in[5];
    const float* b_edge   = (const float*)d_in[6];
    const float* W_gnn    = (const float*)d_in[7];
    const float* b_gnn    = (const float*)d_in[8];
    const float* W_top    = (const float*)d_in[9];
    const float* b_top    = (const float*)d_in[10];
    const float* ln_scale = (const float*)d_in[11];
    const float* ln_bias  = (const float*)d_in[12];

    float *node_h, *agg, *agg_base, *escratch, *edot, *wcombo;
    cudaGetSymbolAddress((void**)&node_h,   g_node_h);
    cudaGetSymbolAddress((void**)&agg,      g_agg);
    cudaGetSymbolAddress((void**)&agg_base, g_agg_base);
    cudaGetSymbolAddress((void**)&escratch, g_escratch);
    cudaGetSymbolAddress((void**)&edot,     g_edot);
    cudaGetSymbolAddress((void**)&wcombo,   g_wcombo);
    float* eaggF   = escratch;             // [NN, 64] (precompute phase)
    float* deg     = escratch + NN * 64;   // [NN]
    float2* sdot2  = (float2*)escratch;    // [NN] (layer phase; reuses eaggF region)

    float* out_node = (float*)d_out;                       // [NN, H]
    float* out_ew   = (float*)d_out + (size_t)NN * H;      // [NE]

    const int* srcp = edge_indices;
    const int* dstp = edge_indices + NE;

    const int smem_e128 = (128 * H + 32 * 128) * 4;        // 80 KB
    const int smem_e64  = (64 * H + 32 * 64) * 4;          // 40 KB
    const int smem_gnn  = (256 * H + 64 * 256) * 4;        // 192 KB
    cudaFuncSetAttribute((const void*)embed_kernel<128, false, true>,
                         cudaFuncAttributeMaxDynamicSharedMemorySize, smem_e128);
    cudaFuncSetAttribute((const void*)embed_kernel<64, true, false>,
                         cudaFuncAttributeMaxDynamicSharedMemorySize, smem_e64);
    cudaFuncSetAttribute((const void*)gnn_kernel<false>,
                         cudaFuncAttributeMaxDynamicSharedMemorySize, smem_gnn);
    cudaFuncSetAttribute((const void*)gnn_kernel<true>,
                         cudaFuncAttributeMaxDynamicSharedMemorySize, smem_gnn);

    // --- one-time precompute ---
    combo_kernel<<<1, 64>>>(W_edge, W_top, b_edge, b_top, wcombo);
    zero_kernel<<<(NN * 65 / 4 + 255) / 256, 256>>>((float4*)escratch, NN * 65 / 4);
    zero_kernel<<<NN * H / 4 / 256, 256>>>((float4*)agg, NN * H / 4);
    edge_pre_kernel<<<NE / 8, 256>>>(edge_features, dstp, wcombo, eaggF, deg, edot);
    embed_kernel<64, true, false><<<512, 256, smem_e64>>>(
        eaggF, W_edge, b_edge, deg, nullptr, agg_base, nullptr, NN);
    embed_kernel<128, false, true><<<512, 256, smem_e128>>>(
        node_features, W_node, b_node, nullptr, W_top, node_h, sdot2, NN);

    // --- layers ---
    for (int i = 0; i < 3; i++) {
        if (i == 2)
            edge_slim_kernel<true><<<NE / 8, 256>>>(node_h, srcp, dstp, sdot2, edot, agg, out_ew);
        else
            edge_slim_kernel<false><<<NE / 8, 256>>>(node_h, srcp, dstp, sdot2, edot, agg, out_ew);
        const float* Wl  = W_gnn + (size_t)i * 256 * H;
        const float* bl  = b_gnn + i * H;
        const float* lsl = ln_scale + i * H;
        const float* lbl = ln_bias + i * H;
        if (i == 2)
            gnn_kernel<true><<<148, 512, smem_gnn>>>(node_h, agg, agg_base, Wl, bl, lsl, lbl,
                                                     W_top, out_node, sdot2, NN);
        else
            gnn_kernel<false><<<148, 512, smem_gnn>>>(node_h, agg, agg_base, Wl, bl, lsl, lbl,
                                                      W_top, node_h, sdot2, NN);
    }
}